// round 9
// baseline (speedup 1.0000x reference)
#include <cuda_runtime.h>
#include <cuda_bf16.h>
#include <cstdint>
#include <math.h>

#define ED 1024
#define NT 8192

// ---------------- device scratch (no runtime allocation allowed) -------------
__device__ float g_S[(size_t)NT * NT];                       // 256 MB logits
__device__ __nv_bfloat16 g_Xh[(size_t)NT * ED], g_Xl[(size_t)NT * ED];
__device__ __nv_bfloat16 g_XTh[(size_t)ED * NT], g_XTl[(size_t)ED * NT];
__device__ __nv_bfloat16 g_Wqth[(size_t)ED * ED], g_Wqtl[(size_t)ED * ED];
__device__ __nv_bfloat16 g_Wkth[(size_t)ED * ED], g_Wktl[(size_t)ED * ED];
__device__ __nv_bfloat16 g_Qh[(size_t)NT * ED], g_Ql[(size_t)NT * ED];
__device__ __nv_bfloat16 g_Kh[(size_t)NT * ED], g_Kl[(size_t)NT * ED];
__device__ __nv_bfloat16 g_Ph[(size_t)NT * NT], g_Pl[(size_t)NT * NT];    // 256 MB

// ---------------- helpers ----------------------------------------------------
__device__ __forceinline__ uint32_t smem_to_u32(const void* p) {
    uint32_t a;
    asm("{ .reg .u64 t; cvta.to.shared.u64 t, %1; cvt.u32.u64 %0, t; }" : "=r"(a) : "l"(p));
    return a;
}
__device__ __forceinline__ void cp16(uint32_t s, const void* g) {
    asm volatile("cp.async.cg.shared.global [%0], [%1], 16;" :: "r"(s), "l"(g));
}
#define CP_COMMIT() asm volatile("cp.async.commit_group;" ::: "memory")
#define CP_WAIT0()  asm volatile("cp.async.wait_group 0;" ::: "memory")
#define CP_WAIT1()  asm volatile("cp.async.wait_group 1;" ::: "memory")

__device__ __forceinline__ void mma16816(float* d, const uint32_t* a, const uint32_t* b) {
    asm volatile("mma.sync.aligned.m16n8k16.row.col.f32.bf16.bf16.f32 "
                 "{%0,%1,%2,%3}, {%4,%5,%6,%7}, {%8,%9}, {%0,%1,%2,%3};"
                 : "+f"(d[0]), "+f"(d[1]), "+f"(d[2]), "+f"(d[3])
                 : "r"(a[0]), "r"(a[1]), "r"(a[2]), "r"(a[3]), "r"(b[0]), "r"(b[1]));
}
__device__ __forceinline__ void ldsm4(uint32_t* r, uint32_t addr) {
    asm volatile("ldmatrix.sync.aligned.m8n8.x4.shared.b16 {%0,%1,%2,%3}, [%4];"
                 : "=r"(r[0]), "=r"(r[1]), "=r"(r[2]), "=r"(r[3]) : "r"(addr));
}

__device__ __forceinline__ uint32_t pack2bf(float a, float b) {
    __nv_bfloat16 ha = __float2bfloat16(a), hb = __float2bfloat16(b);
    return ((uint32_t)__bfloat16_as_ushort(hb) << 16) | __bfloat16_as_ushort(ha);
}

// ---------------- split / transpose ------------------------------------------
__global__ __launch_bounds__(256) void split_k(
    const float* __restrict__ in, __nv_bfloat16* __restrict__ oh,
    __nv_bfloat16* __restrict__ ol, int n4)
{
    int i = blockIdx.x * 256 + threadIdx.x;
    if (i >= n4) return;
    float4 v = ((const float4*)in)[i];
    float hx = __bfloat162float(__float2bfloat16(v.x));
    float hy = __bfloat162float(__float2bfloat16(v.y));
    float hz = __bfloat162float(__float2bfloat16(v.z));
    float hw = __bfloat162float(__float2bfloat16(v.w));
    uint2 ph, pl;
    ph.x = pack2bf(v.x, v.y);           ph.y = pack2bf(v.z, v.w);
    pl.x = pack2bf(v.x - hx, v.y - hy); pl.y = pack2bf(v.z - hz, v.w - hw);
    ((uint2*)oh)[i] = ph;
    ((uint2*)ol)[i] = pl;
}

__global__ __launch_bounds__(1024) void tsplit_k(
    const float* __restrict__ in, __nv_bfloat16* __restrict__ oh,
    __nv_bfloat16* __restrict__ ol, int R, int C)
{
    __shared__ float sm[32][33];
    int c0 = blockIdx.x * 32, r0 = blockIdx.y * 32;
    sm[threadIdx.y][threadIdx.x] = in[(size_t)(r0 + threadIdx.y) * C + c0 + threadIdx.x];
    __syncthreads();
    float v = sm[threadIdx.x][threadIdx.y];
    float h = __bfloat162float(__float2bfloat16(v));
    size_t o = (size_t)(c0 + threadIdx.y) * R + r0 + threadIdx.x;
    oh[o] = __float2bfloat16(v);
    ol[o] = __float2bfloat16(v - h);
}

// ---------------- bf16x3 emulated-fp32 GEMM via mma.sync + ldmatrix ----------
// C[M,N] = alpha * A[M,Kt] @ B[N,Kt]^T.  mode 0: fp32 out. mode 1: bf16 hi/lo out.
// Block 128x128, BK=32, 512 threads / 16 warps (warp tile 32x32),
// 3-stage cp.async pipeline, ONE barrier per chunk, double-buffered fragments.
#define SSTR 40                               // bf16 elements per smem row (pad)
#define STG  (128 * SSTR)                     // elements per stage per matrix
#define NSTAGE 3
#define GEMM_SMEM (4 * NSTAGE * STG * 2)      // 4 matrices * 3 stages = 120KB

__global__ __launch_bounds__(512, 1)
void gemm_mma_k(const __nv_bfloat16* __restrict__ Ah, const __nv_bfloat16* __restrict__ Al,
                const __nv_bfloat16* __restrict__ Bh, const __nv_bfloat16* __restrict__ Bl,
                int Kt, int Nt, int mode, float alpha,
                float* __restrict__ Cf, __nv_bfloat16* __restrict__ Ch,
                __nv_bfloat16* __restrict__ Cl)
{
    extern __shared__ __nv_bfloat16 smem[];
    __nv_bfloat16* sAh = smem;
    __nv_bfloat16* sAl = smem + NSTAGE * STG;
    __nv_bfloat16* sBh = smem + 2 * NSTAGE * STG;
    __nv_bfloat16* sBl = smem + 3 * NSTAGE * STG;
    const uint32_t uAh = smem_to_u32(sAh), uAl = smem_to_u32(sAl);
    const uint32_t uBh = smem_to_u32(sBh), uBl = smem_to_u32(sBl);

    const int tid = threadIdx.x;
    const int wid = tid >> 5, lid = tid & 31;
    const int wm = wid >> 2, wn = wid & 3;        // 4x4 warp grid, warp tile 32x32
    const int g = lid >> 2, t = lid & 3;
    const int m0 = blockIdx.y * 128, n0 = blockIdx.x * 128;

    // copy thread mapping: 512 threads, one 16B seg per matrix per chunk
    const int crow = tid >> 2, cseg = tid & 3;

    // ldmatrix lane address components
    const int a_row = lid & 15;
    const int a_k8  = ((lid >> 4) & 1) * 8;
    const int b_n   = ((lid >> 4) & 1) * 8 + (lid & 7);
    const int b_k8  = ((lid >> 3) & 1) * 8;

    float acc[2][4][4] = {};
    const int nk = Kt >> 5;

    auto load_chunk = [&](int st, int kb) {
        uint32_t sb = (uint32_t)(st * STG) * 2 + (uint32_t)(crow * SSTR + cseg * 8) * 2;
        size_t gA = (size_t)(m0 + crow) * Kt + kb + cseg * 8;
        size_t gB = (size_t)(n0 + crow) * Kt + kb + cseg * 8;
        cp16(uAh + sb, Ah + gA);
        cp16(uAl + sb, Al + gA);
        cp16(uBh + sb, Bh + gB);
        cp16(uBl + sb, Bl + gB);
    };

    // fragment buffers (double-buffered over the two ks sub-chunks)
    uint32_t aH[2][2][4], aL[2][2][4], bH[2][2][4], bL[2][2][4];

    auto load_frags = [&](int f, uint32_t st2, int kk) {
#pragma unroll
        for (int mt = 0; mt < 2; mt++) {
            uint32_t off = st2 + (uint32_t)((wm * 32 + mt * 16 + a_row) * SSTR + kk + a_k8) * 2;
            ldsm4(aH[f][mt], uAh + off);
            ldsm4(aL[f][mt], uAl + off);
        }
#pragma unroll
        for (int np = 0; np < 2; np++) {
            uint32_t off = st2 + (uint32_t)((wn * 32 + np * 16 + b_n) * SSTR + kk + b_k8) * 2;
            ldsm4(bH[f][np], uBh + off);
            ldsm4(bL[f][np], uBl + off);
        }
    };

    auto do_mmas = [&](int f) {
#pragma unroll
        for (int mt = 0; mt < 2; mt++)
#pragma unroll
            for (int np = 0; np < 2; np++) {
                mma16816(acc[mt][2 * np],     aH[f][mt], &bH[f][np][0]);
                mma16816(acc[mt][2 * np],     aH[f][mt], &bL[f][np][0]);
                mma16816(acc[mt][2 * np],     aL[f][mt], &bH[f][np][0]);
                mma16816(acc[mt][2 * np + 1], aH[f][mt], &bH[f][np][2]);
                mma16816(acc[mt][2 * np + 1], aH[f][mt], &bL[f][np][2]);
                mma16816(acc[mt][2 * np + 1], aL[f][mt], &bH[f][np][2]);
            }
    };

    load_chunk(0, 0);
    CP_COMMIT();
    load_chunk(1, 32);
    CP_COMMIT();

    for (int kc = 0; kc < nk; kc++) {
        if (kc + 1 < nk) { CP_WAIT1(); } else { CP_WAIT0(); }
        __syncthreads();                       // single barrier per chunk
        if (kc + 2 < nk) {
            load_chunk((kc + 2) % NSTAGE, (kc + 2) << 5);
            CP_COMMIT();
        }
        const uint32_t st2 = (uint32_t)((kc % NSTAGE) * STG) * 2;
        load_frags(0, st2, 0);
        load_frags(1, st2, 16);                // overlaps with ks=0 MMAs below
        do_mmas(0);
        do_mmas(1);
    }

    // ---- epilogue: direct stores ----
#pragma unroll
    for (int mt = 0; mt < 2; mt++) {
#pragma unroll
        for (int nt = 0; nt < 4; nt++) {
            int r = m0 + wm * 32 + mt * 16 + g;
            int c = n0 + wn * 32 + nt * 8 + t * 2;
            float d0 = alpha * acc[mt][nt][0], d1 = alpha * acc[mt][nt][1];
            float d2 = alpha * acc[mt][nt][2], d3 = alpha * acc[mt][nt][3];
            if (mode == 0) {
                float2 v0 = { d0, d1 }, v1 = { d2, d3 };
                *(float2*)(Cf + (size_t)r * Nt + c) = v0;
                *(float2*)(Cf + (size_t)(r + 8) * Nt + c) = v1;
            } else {
                float h0 = __bfloat162float(__float2bfloat16(d0));
                float h1 = __bfloat162float(__float2bfloat16(d1));
                float h2 = __bfloat162float(__float2bfloat16(d2));
                float h3 = __bfloat162float(__float2bfloat16(d3));
                *(uint32_t*)(Ch + (size_t)r * Nt + c)       = pack2bf(d0, d1);
                *(uint32_t*)(Ch + (size_t)(r + 8) * Nt + c) = pack2bf(d2, d3);
                *(uint32_t*)(Cl + (size_t)r * Nt + c)       = pack2bf(d0 - h0, d1 - h1);
                *(uint32_t*)(Cl + (size_t)(r + 8) * Nt + c) = pack2bf(d2 - h2, d3 - h3);
            }
        }
    }
}

// --------------- softmax: fp32 in, bf16 hi/lo split out ----------------------
__global__ __launch_bounds__(256) void softmax_row_k(
    const float* __restrict__ S, __nv_bfloat16* __restrict__ Ph,
    __nv_bfloat16* __restrict__ Pl, int N)
{
    __shared__ float buf[NT];
    __shared__ float red[8];
    const int tid = threadIdx.x;
    const float* row = S + (size_t)blockIdx.x * N;
    __nv_bfloat16* ph = Ph + (size_t)blockIdx.x * N;
    __nv_bfloat16* pl = Pl + (size_t)blockIdx.x * N;

    float m = -1e30f;
    for (int i = tid * 4; i < N; i += 1024) {
        float4 v = *(const float4*)(row + i);
        *(float4*)&buf[i] = v;
        m = fmaxf(m, fmaxf(fmaxf(v.x, v.y), fmaxf(v.z, v.w)));
    }
#pragma unroll
    for (int o = 16; o > 0; o >>= 1) m = fmaxf(m, __shfl_xor_sync(0xffffffffu, m, o));
    if ((tid & 31) == 0) red[tid >> 5] = m;
    __syncthreads();
    if (tid < 32) {
        float v = (tid < 8) ? red[tid] : -1e30f;
#pragma unroll
        for (int o = 4; o > 0; o >>= 1) v = fmaxf(v, __shfl_xor_sync(0xffffffffu, v, o));
        if (tid == 0) red[0] = v;
    }
    __syncthreads();
    const float gm = red[0];
    __syncthreads();

    float s = 0.0f;
    for (int i = tid * 4; i < N; i += 1024) {
        float4 v = *(float4*)&buf[i];
        v.x = expf(v.x - gm); v.y = expf(v.y - gm);
        v.z = expf(v.z - gm); v.w = expf(v.w - gm);
        *(float4*)&buf[i] = v;
        s += (v.x + v.y) + (v.z + v.w);
    }
#pragma unroll
    for (int o = 16; o > 0; o >>= 1) s += __shfl_xor_sync(0xffffffffu, s, o);
    if ((tid & 31) == 0) red[tid >> 5] = s;
    __syncthreads();
    if (tid < 32) {
        float v = (tid < 8) ? red[tid] : 0.0f;
#pragma unroll
        for (int o = 4; o > 0; o >>= 1) v += __shfl_xor_sync(0xffffffffu, v, o);
        if (tid == 0) red[0] = v;
    }
    __syncthreads();
    const float inv = 1.0f / red[0];

    for (int i = tid * 4; i < N; i += 1024) {
        float4 v = *(float4*)&buf[i];
        v.x *= inv; v.y *= inv; v.z *= inv; v.w *= inv;
        float hx = __bfloat162float(__float2bfloat16(v.x));
        float hy = __bfloat162float(__float2bfloat16(v.y));
        float hz = __bfloat162float(__float2bfloat16(v.z));
        float hw = __bfloat162float(__float2bfloat16(v.w));
        uint2 H, L;
        H.x = pack2bf(v.x, v.y);            H.y = pack2bf(v.z, v.w);
        L.x = pack2bf(v.x - hx, v.y - hy);  L.y = pack2bf(v.z - hz, v.w - hw);
        *(uint2*)(ph + i) = H;
        *(uint2*)(pl + i) = L;
    }
}

// -----------------------------------------------------------------------------
extern "C" void kernel_launch(void* const* d_in, const int* in_sizes, int n_in,
                              void* d_out, int out_size)
{
    const float* Wq = (const float*)d_in[0];
    const float* Wk = (const float*)d_in[1];
    const float* X  = (const float*)d_in[2];
    float* O = (float*)d_out;

    float* S;
    __nv_bfloat16 *Xh, *Xl, *XTh, *XTl, *Wqth, *Wqtl, *Wkth, *Wktl;
    __nv_bfloat16 *Qh, *Ql, *Kh, *Kl, *Ph, *Pl;
    cudaGetSymbolAddress((void**)&S, g_S);
    cudaGetSymbolAddress((void**)&Xh, g_Xh);     cudaGetSymbolAddress((void**)&Xl, g_Xl);
    cudaGetSymbolAddress((void**)&XTh, g_XTh);   cudaGetSymbolAddress((void**)&XTl, g_XTl);
    cudaGetSymbolAddress((void**)&Wqth, g_Wqth); cudaGetSymbolAddress((void**)&Wqtl, g_Wqtl);
    cudaGetSymbolAddress((void**)&Wkth, g_Wkth); cudaGetSymbolAddress((void**)&Wktl, g_Wktl);
    cudaGetSymbolAddress((void**)&Qh, g_Qh);     cudaGetSymbolAddress((void**)&Ql, g_Ql);
    cudaGetSymbolAddress((void**)&Kh, g_Kh);     cudaGetSymbolAddress((void**)&Kl, g_Kl);
    cudaGetSymbolAddress((void**)&Ph, g_Ph);     cudaGetSymbolAddress((void**)&Pl, g_Pl);

    cudaFuncSetAttribute(gemm_mma_k, cudaFuncAttributeMaxDynamicSharedMemorySize, GEMM_SMEM);

    // operand prep
    split_k<<<(NT * ED / 4 + 255) / 256, 256>>>(X, Xh, Xl, NT * ED / 4);
    tsplit_k<<<dim3(ED / 32, ED / 32), dim3(32, 32)>>>(Wq, Wqth, Wqtl, ED, ED);
    tsplit_k<<<dim3(ED / 32, ED / 32), dim3(32, 32)>>>(Wk, Wkth, Wktl, ED, ED);
    tsplit_k<<<dim3(ED / 32, NT / 32), dim3(32, 32)>>>(X, XTh, XTl, NT, ED);

    // Q = X @ Wq, K = X @ Wk  (epilogue emits bf16 hi/lo splits directly)
    gemm_mma_k<<<dim3(ED / 128, NT / 128), 512, GEMM_SMEM>>>(
        Xh, Xl, Wqth, Wqtl, ED, ED, 1, 1.0f, nullptr, Qh, Ql);
    gemm_mma_k<<<dim3(ED / 128, NT / 128), 512, GEMM_SMEM>>>(
        Xh, Xl, Wkth, Wktl, ED, ED, 1, 1.0f, nullptr, Kh, Kl);

    // S = (Q @ K^T) / 32
    gemm_mma_k<<<dim3(NT / 128, NT / 128), 512, GEMM_SMEM>>>(
        Qh, Ql, Kh, Kl, ED, NT, 0, 0.03125f, S, nullptr, nullptr);

    // P = softmax(S), split to bf16 hi/lo
    softmax_row_k<<<NT, 256>>>(S, Ph, Pl, NT);

    // O = P @ X
    gemm_mma_k<<<dim3(ED / 128, NT / 128), 512, GEMM_SMEM>>>(
        Ph, Pl, XTh, XTl, NT, ED, 0, 1.0f, O, nullptr, nullptr);
}

// round 10
// speedup vs baseline: 1.1208x; 1.1208x over previous
#include <cuda_runtime.h>
#include <cuda_bf16.h>
#include <cstdint>
#include <math.h>

#define ED 1024
#define NT 8192

// ---------------- device scratch (no runtime allocation allowed) -------------
__device__ float g_S[(size_t)NT * NT];                       // 256 MB logits
__device__ __nv_bfloat16 g_Xh[(size_t)NT * ED], g_Xl[(size_t)NT * ED];
__device__ __nv_bfloat16 g_XTh[(size_t)ED * NT], g_XTl[(size_t)ED * NT];
__device__ __nv_bfloat16 g_Wqth[(size_t)ED * ED], g_Wqtl[(size_t)ED * ED];
__device__ __nv_bfloat16 g_Wkth[(size_t)ED * ED], g_Wktl[(size_t)ED * ED];
__device__ __nv_bfloat16 g_Qh[(size_t)NT * ED], g_Ql[(size_t)NT * ED];
__device__ __nv_bfloat16 g_Kh[(size_t)NT * ED], g_Kl[(size_t)NT * ED];
__device__ __nv_bfloat16 g_Ph[(size_t)NT * NT], g_Pl[(size_t)NT * NT];    // 256 MB

// ---------------- helpers ----------------------------------------------------
__device__ __forceinline__ uint32_t smem_to_u32(const void* p) {
    uint32_t a;
    asm("{ .reg .u64 t; cvta.to.shared.u64 t, %1; cvt.u32.u64 %0, t; }" : "=r"(a) : "l"(p));
    return a;
}
__device__ __forceinline__ void cp16(uint32_t s, const void* g) {
    asm volatile("cp.async.cg.shared.global [%0], [%1], 16;" :: "r"(s), "l"(g));
}
#define CP_COMMIT() asm volatile("cp.async.commit_group;" ::: "memory")
#define CP_WAIT0()  asm volatile("cp.async.wait_group 0;" ::: "memory")
#define CP_WAIT1()  asm volatile("cp.async.wait_group 1;" ::: "memory")

__device__ __forceinline__ void mma16816(float* d, const uint32_t* a, const uint32_t* b) {
    asm volatile("mma.sync.aligned.m16n8k16.row.col.f32.bf16.bf16.f32 "
                 "{%0,%1,%2,%3}, {%4,%5,%6,%7}, {%8,%9}, {%0,%1,%2,%3};"
                 : "+f"(d[0]), "+f"(d[1]), "+f"(d[2]), "+f"(d[3])
                 : "r"(a[0]), "r"(a[1]), "r"(a[2]), "r"(a[3]), "r"(b[0]), "r"(b[1]));
}
__device__ __forceinline__ void ldsm4(uint32_t* r, uint32_t addr) {
    asm volatile("ldmatrix.sync.aligned.m8n8.x4.shared.b16 {%0,%1,%2,%3}, [%4];"
                 : "=r"(r[0]), "=r"(r[1]), "=r"(r[2]), "=r"(r[3]) : "r"(addr));
}

__device__ __forceinline__ uint32_t pack2bf(float a, float b) {
    __nv_bfloat16 ha = __float2bfloat16(a), hb = __float2bfloat16(b);
    return ((uint32_t)__bfloat16_as_ushort(hb) << 16) | __bfloat16_as_ushort(ha);
}

// ---------------- split / transpose ------------------------------------------
__global__ __launch_bounds__(256) void split_k(
    const float* __restrict__ in, __nv_bfloat16* __restrict__ oh,
    __nv_bfloat16* __restrict__ ol, int n4)
{
    int i = blockIdx.x * 256 + threadIdx.x;
    if (i >= n4) return;
    float4 v = ((const float4*)in)[i];
    float hx = __bfloat162float(__float2bfloat16(v.x));
    float hy = __bfloat162float(__float2bfloat16(v.y));
    float hz = __bfloat162float(__float2bfloat16(v.z));
    float hw = __bfloat162float(__float2bfloat16(v.w));
    uint2 ph, pl;
    ph.x = pack2bf(v.x, v.y);           ph.y = pack2bf(v.z, v.w);
    pl.x = pack2bf(v.x - hx, v.y - hy); pl.y = pack2bf(v.z - hz, v.w - hw);
    ((uint2*)oh)[i] = ph;
    ((uint2*)ol)[i] = pl;
}

__global__ __launch_bounds__(1024) void tsplit_k(
    const float* __restrict__ in, __nv_bfloat16* __restrict__ oh,
    __nv_bfloat16* __restrict__ ol, int R, int C)
{
    __shared__ float sm[32][33];
    int c0 = blockIdx.x * 32, r0 = blockIdx.y * 32;
    sm[threadIdx.y][threadIdx.x] = in[(size_t)(r0 + threadIdx.y) * C + c0 + threadIdx.x];
    __syncthreads();
    float v = sm[threadIdx.x][threadIdx.y];
    float h = __bfloat162float(__float2bfloat16(v));
    size_t o = (size_t)(c0 + threadIdx.y) * R + r0 + threadIdx.x;
    oh[o] = __float2bfloat16(v);
    ol[o] = __float2bfloat16(v - h);
}

// ---------------- bf16x3 emulated-fp32 GEMM via mma.sync + ldmatrix ----------
// C[M,N] = alpha * A[M,Kt] @ B[N,Kt]^T.  mode 0: fp32 out. mode 1: bf16 hi/lo out.
// CTA tile 256x128, BK=32, 8 warps (4x2), warp tile 64x64.
// 3-stage cp.async pipeline (180 KB smem), single barrier per chunk.
// High arithmetic intensity: smem fragment traffic = 1/3 of tensor time.
#define SSTR 40                               // bf16 elements per smem row (pad)
#define ASTG (256 * SSTR)                     // A stage elements
#define BSTG (128 * SSTR)                     // B stage elements
#define NSTAGE 3
#define GEMM_SMEM ((2 * NSTAGE * ASTG + 2 * NSTAGE * BSTG) * 2)   // 184320 B

__global__ __launch_bounds__(256, 1)
void gemm_mma_k(const __nv_bfloat16* __restrict__ Ah, const __nv_bfloat16* __restrict__ Al,
                const __nv_bfloat16* __restrict__ Bh, const __nv_bfloat16* __restrict__ Bl,
                int Kt, int Nt, int mode, float alpha,
                float* __restrict__ Cf, __nv_bfloat16* __restrict__ Ch,
                __nv_bfloat16* __restrict__ Cl)
{
    extern __shared__ __nv_bfloat16 smem[];
    __nv_bfloat16* sAh = smem;
    __nv_bfloat16* sAl = smem + NSTAGE * ASTG;
    __nv_bfloat16* sBh = smem + 2 * NSTAGE * ASTG;
    __nv_bfloat16* sBl = smem + 2 * NSTAGE * ASTG + NSTAGE * BSTG;
    const uint32_t uAh = smem_to_u32(sAh), uAl = smem_to_u32(sAl);
    const uint32_t uBh = smem_to_u32(sBh), uBl = smem_to_u32(sBl);

    const int tid = threadIdx.x;
    const int wid = tid >> 5, lid = tid & 31;
    const int wm = wid >> 1, wn = wid & 1;        // 4x2 warp grid, warp tile 64x64
    const int g = lid >> 2, t = lid & 3;
    const int m0 = blockIdx.y * 256, n0 = blockIdx.x * 128;

    const int crow = tid >> 2, cseg = tid & 3;

    // ldmatrix lane address components
    const int a_row = lid & 15;
    const int a_k8  = ((lid >> 4) & 1) * 8;
    const int b_n   = ((lid >> 4) & 1) * 8 + (lid & 7);
    const int b_k8  = ((lid >> 3) & 1) * 8;

    float acc[4][8][4] = {};                      // 128 regs
    const int nk = Kt >> 5;

    auto load_chunk = [&](int st, int kb) {
        // A: 256 rows x 4 segs = 1024 cp16 per matrix
#pragma unroll
        for (int i = 0; i < 4; i++) {
            int idx = i * 256 + tid;
            int row = idx >> 2, seg = idx & 3;
            uint32_t so = (uint32_t)(st * ASTG + row * SSTR + seg * 8) * 2;
            size_t gA = (size_t)(m0 + row) * Kt + kb + seg * 8;
            cp16(uAh + so, Ah + gA);
            cp16(uAl + so, Al + gA);
        }
        // B: 128 rows x 4 segs = 512 cp16 per matrix
#pragma unroll
        for (int i = 0; i < 2; i++) {
            int idx = i * 256 + tid;
            int row = idx >> 2, seg = idx & 3;
            uint32_t so = (uint32_t)(st * BSTG + row * SSTR + seg * 8) * 2;
            size_t gB = (size_t)(n0 + row) * Kt + kb + seg * 8;
            cp16(uBh + so, Bh + gB);
            cp16(uBl + so, Bl + gB);
        }
    };

    load_chunk(0, 0);
    CP_COMMIT();
    load_chunk(1, 32);
    CP_COMMIT();

    for (int kc = 0; kc < nk; kc++) {
        if (kc + 1 < nk) { CP_WAIT1(); } else { CP_WAIT0(); }
        __syncthreads();                       // single barrier per chunk
        if (kc + 2 < nk) {
            load_chunk((kc + 2) % NSTAGE, (kc + 2) << 5);
            CP_COMMIT();
        }
        const uint32_t stA = (uint32_t)((kc % NSTAGE) * ASTG) * 2;
        const uint32_t stB = (uint32_t)((kc % NSTAGE) * BSTG) * 2;
#pragma unroll
        for (int ks = 0; ks < 2; ks++) {
            const int kk = ks * 16;
            uint32_t aH[4][4], aL[4][4];
#pragma unroll
            for (int mt = 0; mt < 4; mt++) {
                uint32_t off = stA + (uint32_t)((wm * 64 + mt * 16 + a_row) * SSTR + kk + a_k8) * 2;
                ldsm4(aH[mt], uAh + off);
                ldsm4(aL[mt], uAl + off);
            }
            uint32_t bH[4][4], bL[4][4];
#pragma unroll
            for (int np = 0; np < 4; np++) {
                uint32_t off = stB + (uint32_t)((wn * 64 + np * 16 + b_n) * SSTR + kk + b_k8) * 2;
                ldsm4(bH[np], uBh + off);
                ldsm4(bL[np], uBl + off);
            }
#pragma unroll
            for (int mt = 0; mt < 4; mt++)
#pragma unroll
                for (int np = 0; np < 4; np++) {
                    mma16816(acc[mt][2 * np],     aH[mt], &bH[np][0]);
                    mma16816(acc[mt][2 * np],     aH[mt], &bL[np][0]);
                    mma16816(acc[mt][2 * np],     aL[mt], &bH[np][0]);
                    mma16816(acc[mt][2 * np + 1], aH[mt], &bH[np][2]);
                    mma16816(acc[mt][2 * np + 1], aH[mt], &bL[np][2]);
                    mma16816(acc[mt][2 * np + 1], aL[mt], &bH[np][2]);
                }
        }
    }

    // ---- epilogue: direct stores ----
#pragma unroll
    for (int mt = 0; mt < 4; mt++) {
#pragma unroll
        for (int nt = 0; nt < 8; nt++) {
            int r = m0 + wm * 64 + mt * 16 + g;
            int c = n0 + wn * 64 + nt * 8 + t * 2;
            float d0 = alpha * acc[mt][nt][0], d1 = alpha * acc[mt][nt][1];
            float d2 = alpha * acc[mt][nt][2], d3 = alpha * acc[mt][nt][3];
            if (mode == 0) {
                float2 v0 = { d0, d1 }, v1 = { d2, d3 };
                *(float2*)(Cf + (size_t)r * Nt + c) = v0;
                *(float2*)(Cf + (size_t)(r + 8) * Nt + c) = v1;
            } else {
                float h0 = __bfloat162float(__float2bfloat16(d0));
                float h1 = __bfloat162float(__float2bfloat16(d1));
                float h2 = __bfloat162float(__float2bfloat16(d2));
                float h3 = __bfloat162float(__float2bfloat16(d3));
                *(uint32_t*)(Ch + (size_t)r * Nt + c)       = pack2bf(d0, d1);
                *(uint32_t*)(Ch + (size_t)(r + 8) * Nt + c) = pack2bf(d2, d3);
                *(uint32_t*)(Cl + (size_t)r * Nt + c)       = pack2bf(d0 - h0, d1 - h1);
                *(uint32_t*)(Cl + (size_t)(r + 8) * Nt + c) = pack2bf(d2 - h2, d3 - h3);
            }
        }
    }
}

// --------------- softmax: fp32 in, bf16 hi/lo split out ----------------------
__global__ __launch_bounds__(256) void softmax_row_k(
    const float* __restrict__ S, __nv_bfloat16* __restrict__ Ph,
    __nv_bfloat16* __restrict__ Pl, int N)
{
    __shared__ float buf[NT];
    __shared__ float red[8];
    const int tid = threadIdx.x;
    const float* row = S + (size_t)blockIdx.x * N;
    __nv_bfloat16* ph = Ph + (size_t)blockIdx.x * N;
    __nv_bfloat16* pl = Pl + (size_t)blockIdx.x * N;

    float m = -1e30f;
    for (int i = tid * 4; i < N; i += 1024) {
        float4 v = *(const float4*)(row + i);
        *(float4*)&buf[i] = v;
        m = fmaxf(m, fmaxf(fmaxf(v.x, v.y), fmaxf(v.z, v.w)));
    }
#pragma unroll
    for (int o = 16; o > 0; o >>= 1) m = fmaxf(m, __shfl_xor_sync(0xffffffffu, m, o));
    if ((tid & 31) == 0) red[tid >> 5] = m;
    __syncthreads();
    if (tid < 32) {
        float v = (tid < 8) ? red[tid] : -1e30f;
#pragma unroll
        for (int o = 4; o > 0; o >>= 1) v = fmaxf(v, __shfl_xor_sync(0xffffffffu, v, o));
        if (tid == 0) red[0] = v;
    }
    __syncthreads();
    const float gm = red[0];
    __syncthreads();

    float s = 0.0f;
    for (int i = tid * 4; i < N; i += 1024) {
        float4 v = *(float4*)&buf[i];
        v.x = expf(v.x - gm); v.y = expf(v.y - gm);
        v.z = expf(v.z - gm); v.w = expf(v.w - gm);
        *(float4*)&buf[i] = v;
        s += (v.x + v.y) + (v.z + v.w);
    }
#pragma unroll
    for (int o = 16; o > 0; o >>= 1) s += __shfl_xor_sync(0xffffffffu, s, o);
    if ((tid & 31) == 0) red[tid >> 5] = s;
    __syncthreads();
    if (tid < 32) {
        float v = (tid < 8) ? red[tid] : 0.0f;
#pragma unroll
        for (int o = 4; o > 0; o >>= 1) v += __shfl_xor_sync(0xffffffffu, v, o);
        if (tid == 0) red[0] = v;
    }
    __syncthreads();
    const float inv = 1.0f / red[0];

    for (int i = tid * 4; i < N; i += 1024) {
        float4 v = *(float4*)&buf[i];
        v.x *= inv; v.y *= inv; v.z *= inv; v.w *= inv;
        float hx = __bfloat162float(__float2bfloat16(v.x));
        float hy = __bfloat162float(__float2bfloat16(v.y));
        float hz = __bfloat162float(__float2bfloat16(v.z));
        float hw = __bfloat162float(__float2bfloat16(v.w));
        uint2 H, L;
        H.x = pack2bf(v.x, v.y);            H.y = pack2bf(v.z, v.w);
        L.x = pack2bf(v.x - hx, v.y - hy);  L.y = pack2bf(v.z - hz, v.w - hw);
        *(uint2*)(ph + i) = H;
        *(uint2*)(pl + i) = L;
    }
}

// -----------------------------------------------------------------------------
extern "C" void kernel_launch(void* const* d_in, const int* in_sizes, int n_in,
                              void* d_out, int out_size)
{
    const float* Wq = (const float*)d_in[0];
    const float* Wk = (const float*)d_in[1];
    const float* X  = (const float*)d_in[2];
    float* O = (float*)d_out;

    float* S;
    __nv_bfloat16 *Xh, *Xl, *XTh, *XTl, *Wqth, *Wqtl, *Wkth, *Wktl;
    __nv_bfloat16 *Qh, *Ql, *Kh, *Kl, *Ph, *Pl;
    cudaGetSymbolAddress((void**)&S, g_S);
    cudaGetSymbolAddress((void**)&Xh, g_Xh);     cudaGetSymbolAddress((void**)&Xl, g_Xl);
    cudaGetSymbolAddress((void**)&XTh, g_XTh);   cudaGetSymbolAddress((void**)&XTl, g_XTl);
    cudaGetSymbolAddress((void**)&Wqth, g_Wqth); cudaGetSymbolAddress((void**)&Wqtl, g_Wqtl);
    cudaGetSymbolAddress((void**)&Wkth, g_Wkth); cudaGetSymbolAddress((void**)&Wktl, g_Wktl);
    cudaGetSymbolAddress((void**)&Qh, g_Qh);     cudaGetSymbolAddress((void**)&Ql, g_Ql);
    cudaGetSymbolAddress((void**)&Kh, g_Kh);     cudaGetSymbolAddress((void**)&Kl, g_Kl);
    cudaGetSymbolAddress((void**)&Ph, g_Ph);     cudaGetSymbolAddress((void**)&Pl, g_Pl);

    cudaFuncSetAttribute(gemm_mma_k, cudaFuncAttributeMaxDynamicSharedMemorySize, GEMM_SMEM);

    // operand prep
    split_k<<<(NT * ED / 4 + 255) / 256, 256>>>(X, Xh, Xl, NT * ED / 4);
    tsplit_k<<<dim3(ED / 32, ED / 32), dim3(32, 32)>>>(Wq, Wqth, Wqtl, ED, ED);
    tsplit_k<<<dim3(ED / 32, ED / 32), dim3(32, 32)>>>(Wk, Wkth, Wktl, ED, ED);
    tsplit_k<<<dim3(ED / 32, NT / 32), dim3(32, 32)>>>(X, XTh, XTl, NT, ED);

    // Q = X @ Wq, K = X @ Wk  (epilogue emits bf16 hi/lo splits directly)
    gemm_mma_k<<<dim3(ED / 128, NT / 256), 256, GEMM_SMEM>>>(
        Xh, Xl, Wqth, Wqtl, ED, ED, 1, 1.0f, nullptr, Qh, Ql);
    gemm_mma_k<<<dim3(ED / 128, NT / 256), 256, GEMM_SMEM>>>(
        Xh, Xl, Wkth, Wktl, ED, ED, 1, 1.0f, nullptr, Kh, Kl);

    // S = (Q @ K^T) / 32
    gemm_mma_k<<<dim3(NT / 128, NT / 256), 256, GEMM_SMEM>>>(
        Qh, Ql, Kh, Kl, ED, NT, 0, 0.03125f, S, nullptr, nullptr);

    // P = softmax(S), split to bf16 hi/lo
    softmax_row_k<<<NT, 256>>>(S, Ph, Pl, NT);

    // O = P @ X
    gemm_mma_k<<<dim3(ED / 128, NT / 256), 256, GEMM_SMEM>>>(
        Ph, Pl, XTh, XTl, NT, ED, 0, 1.0f, O, nullptr, nullptr);
}

// round 12
// speedup vs baseline: 1.2032x; 1.0735x over previous
#include <cuda_runtime.h>
#include <cuda_bf16.h>
#include <cstdint>
#include <math.h>

#define ED 1024
#define NT 8192

// ---------------- device scratch (no runtime allocation allowed) -------------
__device__ float g_S[(size_t)NT * NT];                       // 256 MB logits
__device__ __nv_bfloat16 g_Xh[(size_t)NT * ED], g_Xl[(size_t)NT * ED];
__device__ __nv_bfloat16 g_XTh[(size_t)ED * NT], g_XTl[(size_t)ED * NT];
__device__ __nv_bfloat16 g_Wqth[(size_t)ED * ED], g_Wqtl[(size_t)ED * ED];
__device__ __nv_bfloat16 g_Wkth[(size_t)ED * ED], g_Wktl[(size_t)ED * ED];
__device__ __nv_bfloat16 g_Qh[(size_t)NT * ED], g_Ql[(size_t)NT * ED];
__device__ __nv_bfloat16 g_Kh[(size_t)NT * ED], g_Kl[(size_t)NT * ED];
__device__ __nv_bfloat16 g_Ph[(size_t)NT * NT], g_Pl[(size_t)NT * NT];    // 256 MB

// ---------------- helpers ----------------------------------------------------
__device__ __forceinline__ uint32_t smem_to_u32(const void* p) {
    uint32_t a;
    asm("{ .reg .u64 t; cvta.to.shared.u64 t, %1; cvt.u32.u64 %0, t; }" : "=r"(a) : "l"(p));
    return a;
}
__device__ __forceinline__ void cp16(uint32_t s, const void* g) {
    asm volatile("cp.async.cg.shared.global [%0], [%1], 16;" :: "r"(s), "l"(g));
}
#define CP_COMMIT() asm volatile("cp.async.commit_group;" ::: "memory")
#define CP_WAIT0()  asm volatile("cp.async.wait_group 0;" ::: "memory")
#define CP_WAIT1()  asm volatile("cp.async.wait_group 1;" ::: "memory")

__device__ __forceinline__ void mma16816(float* d, const uint32_t* a, const uint32_t* b) {
    asm volatile("mma.sync.aligned.m16n8k16.row.col.f32.bf16.bf16.f32 "
                 "{%0,%1,%2,%3}, {%4,%5,%6,%7}, {%8,%9}, {%0,%1,%2,%3};"
                 : "+f"(d[0]), "+f"(d[1]), "+f"(d[2]), "+f"(d[3])
                 : "r"(a[0]), "r"(a[1]), "r"(a[2]), "r"(a[3]), "r"(b[0]), "r"(b[1]));
}
__device__ __forceinline__ void ldsm4(uint32_t* r, uint32_t addr) {
    asm volatile("ldmatrix.sync.aligned.m8n8.x4.shared.b16 {%0,%1,%2,%3}, [%4];"
                 : "=r"(r[0]), "=r"(r[1]), "=r"(r[2]), "=r"(r[3]) : "r"(addr));
}

__device__ __forceinline__ uint32_t pack2bf(float a, float b) {
    __nv_bfloat16 ha = __float2bfloat16(a), hb = __float2bfloat16(b);
    return ((uint32_t)__bfloat16_as_ushort(hb) << 16) | __bfloat16_as_ushort(ha);
}

// XOR swizzle: dense 32-elt (64B) rows, 16B chunk c at row r lives at chunk c^((r>>1)&3).
// Element offset within a stage for (row, chunk):
__device__ __forceinline__ uint32_t swz(int row, int chunk) {
    return (uint32_t)((row << 5) + ((chunk ^ ((row >> 1) & 3)) << 3));
}

// ---------------- split / transpose ------------------------------------------
__global__ __launch_bounds__(256) void split_k(
    const float* __restrict__ in, __nv_bfloat16* __restrict__ oh,
    __nv_bfloat16* __restrict__ ol, int n4)
{
    int i = blockIdx.x * 256 + threadIdx.x;
    if (i >= n4) return;
    float4 v = ((const float4*)in)[i];
    float hx = __bfloat162float(__float2bfloat16(v.x));
    float hy = __bfloat162float(__float2bfloat16(v.y));
    float hz = __bfloat162float(__float2bfloat16(v.z));
    float hw = __bfloat162float(__float2bfloat16(v.w));
    uint2 ph, pl;
    ph.x = pack2bf(v.x, v.y);           ph.y = pack2bf(v.z, v.w);
    pl.x = pack2bf(v.x - hx, v.y - hy); pl.y = pack2bf(v.z - hz, v.w - hw);
    ((uint2*)oh)[i] = ph;
    ((uint2*)ol)[i] = pl;
}

__global__ __launch_bounds__(1024) void tsplit_k(
    const float* __restrict__ in, __nv_bfloat16* __restrict__ oh,
    __nv_bfloat16* __restrict__ ol, int R, int C)
{
    __shared__ float sm[32][33];
    int c0 = blockIdx.x * 32, r0 = blockIdx.y * 32;
    sm[threadIdx.y][threadIdx.x] = in[(size_t)(r0 + threadIdx.y) * C + c0 + threadIdx.x];
    __syncthreads();
    float v = sm[threadIdx.x][threadIdx.y];
    float h = __bfloat162float(__float2bfloat16(v));
    size_t o = (size_t)(c0 + threadIdx.y) * R + r0 + threadIdx.x;
    oh[o] = __float2bfloat16(v);
    ol[o] = __float2bfloat16(v - h);
}

// ---------------- bf16x3 emulated-fp32 GEMM via mma.sync + ldmatrix ----------
// C[M,N] = alpha * A[M,Kt] @ B[N,Kt]^T.  mode 0: fp32 out. mode 1: bf16 hi/lo out.
// Block 128x128, BK=32, 8 warps (warp tile 32x64), 3-stage cp.async pipeline,
// XOR-swizzled dense smem (no pad): 96 KB -> 2 CTAs/SM, ONE barrier per chunk.
// dual: grid.x doubled; upper half uses Bh2/Bl2 -> Ch2/Cl2 (merged projections).
#define STG  (128 * 32)                       // elements per stage per matrix
#define NSTAGE 3
#define GEMM_SMEM (4 * NSTAGE * STG * 2)      // 96 KB

__global__ __launch_bounds__(256, 2)
void gemm_mma_k(const __nv_bfloat16* __restrict__ Ah, const __nv_bfloat16* __restrict__ Al,
                const __nv_bfloat16* __restrict__ Bh, const __nv_bfloat16* __restrict__ Bl,
                const __nv_bfloat16* __restrict__ Bh2, const __nv_bfloat16* __restrict__ Bl2,
                int Kt, int Nt, int mode, int dual, float alpha,
                float* __restrict__ Cf, __nv_bfloat16* __restrict__ Ch,
                __nv_bfloat16* __restrict__ Cl,
                __nv_bfloat16* __restrict__ Ch2, __nv_bfloat16* __restrict__ Cl2)
{
    extern __shared__ __nv_bfloat16 smem[];
    __nv_bfloat16* sAh = smem;
    __nv_bfloat16* sAl = smem + NSTAGE * STG;
    __nv_bfloat16* sBh = smem + 2 * NSTAGE * STG;
    __nv_bfloat16* sBl = smem + 3 * NSTAGE * STG;
    const uint32_t uAh = smem_to_u32(sAh), uAl = smem_to_u32(sAl);
    const uint32_t uBh = smem_to_u32(sBh), uBl = smem_to_u32(sBl);

    const int tid = threadIdx.x;
    const int wid = tid >> 5, lid = tid & 31;
    const int wm = wid >> 1, wn = wid & 1;        // 4x2 warp grid
    const int g = lid >> 2, t = lid & 3;

    // dual-projection block remap
    int bx = blockIdx.x;
    const __nv_bfloat16* pBh = Bh;
    const __nv_bfloat16* pBl = Bl;
    __nv_bfloat16* pCh = Ch;
    __nv_bfloat16* pCl = Cl;
    const int nblk = Nt >> 7;
    if (dual && bx >= nblk) {
        bx -= nblk;
        pBh = Bh2; pBl = Bl2; pCh = Ch2; pCl = Cl2;
    }
    const int m0 = blockIdx.y * 128, n0 = bx * 128;

    const int crow = tid >> 2, cseg = tid & 3;

    // ldmatrix lane address components
    const int a_row = lid & 15;
    const int a_c   = (lid >> 4) & 1;             // k chunk half (0/1)
    const int b_n   = ((lid >> 4) & 1) * 8 + (lid & 7);
    const int b_c   = (lid >> 3) & 1;             // k chunk half (0/1)

    float acc[2][8][4] = {};
    const int nk = Kt >> 5;

    auto load_chunk = [&](int st, int kb) {
        uint32_t so = (uint32_t)(st * STG) * 2;
#pragma unroll
        for (int h = 0; h < 2; h++) {
            int row = crow + h * 64;
            uint32_t sb = so + swz(row, cseg) * 2;
            size_t gA = (size_t)(m0 + row) * Kt + kb + cseg * 8;
            size_t gB = (size_t)(n0 + row) * Kt + kb + cseg * 8;
            cp16(uAh + sb, Ah + gA);
            cp16(uAl + sb, Al + gA);
            cp16(uBh + sb, pBh + gB);
            cp16(uBl + sb, pBl + gB);
        }
    };

    load_chunk(0, 0);
    CP_COMMIT();
    load_chunk(1, 32);
    CP_COMMIT();

    for (int kc = 0; kc < nk; kc++) {
        if (kc + 1 < nk) { CP_WAIT1(); } else { CP_WAIT0(); }
        __syncthreads();                        // single barrier per chunk

        const uint32_t st2 = (uint32_t)((kc % NSTAGE) * STG) * 2;

        // ---- ks = 0 fragments first, so prefetch issue overlaps MMAs ----
        uint32_t aH[2][4], aL[2][4], bH[4][4], bL[4][4];
#pragma unroll
        for (int mt = 0; mt < 2; mt++) {
            uint32_t off = st2 + swz(wm * 32 + mt * 16 + a_row, a_c) * 2;
            ldsm4(aH[mt], uAh + off);
            ldsm4(aL[mt], uAl + off);
        }
#pragma unroll
        for (int np = 0; np < 4; np++) {
            uint32_t off = st2 + swz(wn * 64 + np * 16 + b_n, b_c) * 2;
            ldsm4(bH[np], uBh + off);
            ldsm4(bL[np], uBl + off);
        }

        if (kc + 2 < nk) {
            load_chunk((kc + 2) % NSTAGE, (kc + 2) << 5);
            CP_COMMIT();
        }

#pragma unroll
        for (int mt = 0; mt < 2; mt++)
#pragma unroll
            for (int np = 0; np < 4; np++) {
                mma16816(acc[mt][2 * np],     aH[mt], &bH[np][0]);
                mma16816(acc[mt][2 * np],     aH[mt], &bL[np][0]);
                mma16816(acc[mt][2 * np],     aL[mt], &bH[np][0]);
                mma16816(acc[mt][2 * np + 1], aH[mt], &bH[np][2]);
                mma16816(acc[mt][2 * np + 1], aH[mt], &bL[np][2]);
                mma16816(acc[mt][2 * np + 1], aL[mt], &bH[np][2]);
            }

        // ---- ks = 1 (k chunks 2,3) ----
#pragma unroll
        for (int mt = 0; mt < 2; mt++) {
            uint32_t off = st2 + swz(wm * 32 + mt * 16 + a_row, 2 + a_c) * 2;
            ldsm4(aH[mt], uAh + off);
            ldsm4(aL[mt], uAl + off);
        }
#pragma unroll
        for (int np = 0; np < 4; np++) {
            uint32_t off = st2 + swz(wn * 64 + np * 16 + b_n, 2 + b_c) * 2;
            ldsm4(bH[np], uBh + off);
            ldsm4(bL[np], uBl + off);
        }
#pragma unroll
        for (int mt = 0; mt < 2; mt++)
#pragma unroll
            for (int np = 0; np < 4; np++) {
                mma16816(acc[mt][2 * np],     aH[mt], &bH[np][0]);
                mma16816(acc[mt][2 * np],     aH[mt], &bL[np][0]);
                mma16816(acc[mt][2 * np],     aL[mt], &bH[np][0]);
                mma16816(acc[mt][2 * np + 1], aH[mt], &bH[np][2]);
                mma16816(acc[mt][2 * np + 1], aH[mt], &bL[np][2]);
                mma16816(acc[mt][2 * np + 1], aL[mt], &bH[np][2]);
            }
    }

    // ---- epilogue: direct stores ----
#pragma unroll
    for (int mt = 0; mt < 2; mt++) {
#pragma unroll
        for (int nt = 0; nt < 8; nt++) {
            int r = m0 + wm * 32 + mt * 16 + g;
            int c = n0 + wn * 64 + nt * 8 + t * 2;
            float d0 = alpha * acc[mt][nt][0], d1 = alpha * acc[mt][nt][1];
            float d2 = alpha * acc[mt][nt][2], d3 = alpha * acc[mt][nt][3];
            if (mode == 0) {
                float2 v0 = { d0, d1 }, v1 = { d2, d3 };
                *(float2*)(Cf + (size_t)r * Nt + c) = v0;
                *(float2*)(Cf + (size_t)(r + 8) * Nt + c) = v1;
            } else {
                float h0 = __bfloat162float(__float2bfloat16(d0));
                float h1 = __bfloat162float(__float2bfloat16(d1));
                float h2 = __bfloat162float(__float2bfloat16(d2));
                float h3 = __bfloat162float(__float2bfloat16(d3));
                *(uint32_t*)(pCh + (size_t)r * Nt + c)       = pack2bf(d0, d1);
                *(uint32_t*)(pCh + (size_t)(r + 8) * Nt + c) = pack2bf(d2, d3);
                *(uint32_t*)(pCl + (size_t)r * Nt + c)       = pack2bf(d0 - h0, d1 - h1);
                *(uint32_t*)(pCl + (size_t)(r + 8) * Nt + c) = pack2bf(d2 - h2, d3 - h3);
            }
        }
    }
}

// --------------- softmax: fp32 in, bf16 hi/lo split out ----------------------
__global__ __launch_bounds__(256) void softmax_row_k(
    const float* __restrict__ S, __nv_bfloat16* __restrict__ Ph,
    __nv_bfloat16* __restrict__ Pl, int N)
{
    __shared__ float buf[NT];
    __shared__ float red[8];
    const int tid = threadIdx.x;
    const float* row = S + (size_t)blockIdx.x * N;
    __nv_bfloat16* ph = Ph + (size_t)blockIdx.x * N;
    __nv_bfloat16* pl = Pl + (size_t)blockIdx.x * N;

    float m = -1e30f;
    for (int i = tid * 4; i < N; i += 1024) {
        float4 v = *(const float4*)(row + i);
        *(float4*)&buf[i] = v;
        m = fmaxf(m, fmaxf(fmaxf(v.x, v.y), fmaxf(v.z, v.w)));
    }
#pragma unroll
    for (int o = 16; o > 0; o >>= 1) m = fmaxf(m, __shfl_xor_sync(0xffffffffu, m, o));
    if ((tid & 31) == 0) red[tid >> 5] = m;
    __syncthreads();
    if (tid < 32) {
        float v = (tid < 8) ? red[tid] : -1e30f;
#pragma unroll
        for (int o = 4; o > 0; o >>= 1) v = fmaxf(v, __shfl_xor_sync(0xffffffffu, v, o));
        if (tid == 0) red[0] = v;
    }
    __syncthreads();
    const float gm = red[0];
    __syncthreads();

    float s = 0.0f;
    for (int i = tid * 4; i < N; i += 1024) {
        float4 v = *(float4*)&buf[i];
        v.x = expf(v.x - gm); v.y = expf(v.y - gm);
        v.z = expf(v.z - gm); v.w = expf(v.w - gm);
        *(float4*)&buf[i] = v;
        s += (v.x + v.y) + (v.z + v.w);
    }
#pragma unroll
    for (int o = 16; o > 0; o >>= 1) s += __shfl_xor_sync(0xffffffffu, s, o);
    if ((tid & 31) == 0) red[tid >> 5] = s;
    __syncthreads();
    if (tid < 32) {
        float v = (tid < 8) ? red[tid] : 0.0f;
#pragma unroll
        for (int o = 4; o > 0; o >>= 1) v += __shfl_xor_sync(0xffffffffu, v, o);
        if (tid == 0) red[0] = v;
    }
    __syncthreads();
    const float inv = 1.0f / red[0];

    for (int i = tid * 4; i < N; i += 1024) {
        float4 v = *(float4*)&buf[i];
        v.x *= inv; v.y *= inv; v.z *= inv; v.w *= inv;
        float hx = __bfloat162float(__float2bfloat16(v.x));
        float hy = __bfloat162float(__float2bfloat16(v.y));
        float hz = __bfloat162float(__float2bfloat16(v.z));
        float hw = __bfloat162float(__float2bfloat16(v.w));
        uint2 H, L;
        H.x = pack2bf(v.x, v.y);            H.y = pack2bf(v.z, v.w);
        L.x = pack2bf(v.x - hx, v.y - hy);  L.y = pack2bf(v.z - hz, v.w - hw);
        *(uint2*)(ph + i) = H;
        *(uint2*)(pl + i) = L;
    }
}

// -----------------------------------------------------------------------------
extern "C" void kernel_launch(void* const* d_in, const int* in_sizes, int n_in,
                              void* d_out, int out_size)
{
    const float* Wq = (const float*)d_in[0];
    const float* Wk = (const float*)d_in[1];
    const float* X  = (const float*)d_in[2];
    float* O = (float*)d_out;

    float* S;
    __nv_bfloat16 *Xh, *Xl, *XTh, *XTl, *Wqth, *Wqtl, *Wkth, *Wktl;
    __nv_bfloat16 *Qh, *Ql, *Kh, *Kl, *Ph, *Pl;
    cudaGetSymbolAddress((void**)&S, g_S);
    cudaGetSymbolAddress((void**)&Xh, g_Xh);     cudaGetSymbolAddress((void**)&Xl, g_Xl);
    cudaGetSymbolAddress((void**)&XTh, g_XTh);   cudaGetSymbolAddress((void**)&XTl, g_XTl);
    cudaGetSymbolAddress((void**)&Wqth, g_Wqth); cudaGetSymbolAddress((void**)&Wqtl, g_Wqtl);
    cudaGetSymbolAddress((void**)&Wkth, g_Wkth); cudaGetSymbolAddress((void**)&Wktl, g_Wktl);
    cudaGetSymbolAddress((void**)&Qh, g_Qh);     cudaGetSymbolAddress((void**)&Ql, g_Ql);
    cudaGetSymbolAddress((void**)&Kh, g_Kh);     cudaGetSymbolAddress((void**)&Kl, g_Kl);
    cudaGetSymbolAddress((void**)&Ph, g_Ph);     cudaGetSymbolAddress((void**)&Pl, g_Pl);

    cudaFuncSetAttribute(gemm_mma_k, cudaFuncAttributeMaxDynamicSharedMemorySize, GEMM_SMEM);

    // operand prep
    split_k<<<(NT * ED / 4 + 255) / 256, 256>>>(X, Xh, Xl, NT * ED / 4);
    tsplit_k<<<dim3(ED / 32, ED / 32), dim3(32, 32)>>>(Wq, Wqth, Wqtl, ED, ED);
    tsplit_k<<<dim3(ED / 32, ED / 32), dim3(32, 32)>>>(Wk, Wkth, Wktl, ED, ED);
    tsplit_k<<<dim3(ED / 32, NT / 32), dim3(32, 32)>>>(X, XTh, XTl, NT, ED);

    // Q = X @ Wq AND K = X @ Wk in one merged launch (dual=1, grid.x doubled)
    gemm_mma_k<<<dim3(2 * ED / 128, NT / 128), 256, GEMM_SMEM>>>(
        Xh, Xl, Wqth, Wqtl, Wkth, Wktl, ED, ED, 1, 1, 1.0f,
        nullptr, Qh, Ql, Kh, Kl);

    // S = (Q @ K^T) / 32
    gemm_mma_k<<<dim3(NT / 128, NT / 128), 256, GEMM_SMEM>>>(
        Qh, Ql, Kh, Kl, nullptr, nullptr, ED, NT, 0, 0, 0.03125f,
        S, nullptr, nullptr, nullptr, nullptr);

    // P = softmax(S), split to bf16 hi/lo
    softmax_row_k<<<NT, 256>>>(S, Ph, Pl, NT);

    // O = P @ X
    gemm_mma_k<<<dim3(ED / 128, NT / 128), 256, GEMM_SMEM>>>(
        Ph, Pl, XTh, XTl, nullptr, nullptr, NT, ED, 0, 0, 1.0f,
        O, nullptr, nullptr, nullptr, nullptr);
}

// round 14
// speedup vs baseline: 1.5234x; 1.2662x over previous
#include <cuda_runtime.h>
#include <cuda_bf16.h>
#include <cstdint>
#include <math.h>

#define ED 1024
#define NT 8192

// ---------------- device scratch (no runtime allocation allowed) -------------
__device__ float g_S[(size_t)NT * NT];                       // 256 MB logits
__device__ __nv_bfloat16 g_Xh[(size_t)NT * ED], g_Xl[(size_t)NT * ED];
__device__ __nv_bfloat16 g_XTh[(size_t)ED * NT], g_XTl[(size_t)ED * NT];
__device__ __nv_bfloat16 g_Wqth[(size_t)ED * ED], g_Wqtl[(size_t)ED * ED];
__device__ __nv_bfloat16 g_Wkth[(size_t)ED * ED], g_Wktl[(size_t)ED * ED];
__device__ __nv_bfloat16 g_Qh[(size_t)NT * ED], g_Ql[(size_t)NT * ED];
__device__ __nv_bfloat16 g_Kh[(size_t)NT * ED], g_Kl[(size_t)NT * ED];
__device__ __nv_bfloat16 g_Ph[(size_t)NT * NT], g_Pl[(size_t)NT * NT];    // 256 MB

// ---------------- helpers ----------------------------------------------------
__device__ __forceinline__ uint32_t smem_to_u32(const void* p) {
    uint32_t a;
    asm("{ .reg .u64 t; cvta.to.shared.u64 t, %1; cvt.u32.u64 %0, t; }" : "=r"(a) : "l"(p));
    return a;
}
__device__ __forceinline__ void cp16(uint32_t s, const void* g) {
    asm volatile("cp.async.cg.shared.global [%0], [%1], 16;" :: "r"(s), "l"(g));
}
#define CP_COMMIT() asm volatile("cp.async.commit_group;" ::: "memory")
#define CP_WAIT0()  asm volatile("cp.async.wait_group 0;" ::: "memory")
#define CP_WAIT1()  asm volatile("cp.async.wait_group 1;" ::: "memory")

__device__ __forceinline__ void mma16816(float* d, const uint32_t* a, const uint32_t* b) {
    asm volatile("mma.sync.aligned.m16n8k16.row.col.f32.bf16.bf16.f32 "
                 "{%0,%1,%2,%3}, {%4,%5,%6,%7}, {%8,%9}, {%0,%1,%2,%3};"
                 : "+f"(d[0]), "+f"(d[1]), "+f"(d[2]), "+f"(d[3])
                 : "r"(a[0]), "r"(a[1]), "r"(a[2]), "r"(a[3]), "r"(b[0]), "r"(b[1]));
}
__device__ __forceinline__ void ldsm4(uint32_t* r, uint32_t addr) {
    asm volatile("ldmatrix.sync.aligned.m8n8.x4.shared.b16 {%0,%1,%2,%3}, [%4];"
                 : "=r"(r[0]), "=r"(r[1]), "=r"(r[2]), "=r"(r[3]) : "r"(addr));
}

__device__ __forceinline__ uint32_t pack2bf(float a, float b) {
    __nv_bfloat16 ha = __float2bfloat16(a), hb = __float2bfloat16(b);
    return ((uint32_t)__bfloat16_as_ushort(hb) << 16) | __bfloat16_as_ushort(ha);
}

// XOR swizzle: dense 32-elt (64B) rows, 16B chunk c at row r lives at chunk c^((r>>1)&3).
__device__ __forceinline__ uint32_t swz(int row, int chunk) {
    return (uint32_t)((row << 5) + ((chunk ^ ((row >> 1) & 3)) << 3));
}

// ---------------- split / transpose ------------------------------------------
__global__ __launch_bounds__(256) void split_k(
    const float* __restrict__ in, __nv_bfloat16* __restrict__ oh,
    __nv_bfloat16* __restrict__ ol, int n4)
{
    int i = blockIdx.x * 256 + threadIdx.x;
    if (i >= n4) return;
    float4 v = ((const float4*)in)[i];
    float hx = __bfloat162float(__float2bfloat16(v.x));
    float hy = __bfloat162float(__float2bfloat16(v.y));
    float hz = __bfloat162float(__float2bfloat16(v.z));
    float hw = __bfloat162float(__float2bfloat16(v.w));
    uint2 ph, pl;
    ph.x = pack2bf(v.x, v.y);           ph.y = pack2bf(v.z, v.w);
    pl.x = pack2bf(v.x - hx, v.y - hy); pl.y = pack2bf(v.z - hz, v.w - hw);
    ((uint2*)oh)[i] = ph;
    ((uint2*)ol)[i] = pl;
}

__global__ __launch_bounds__(1024) void tsplit_k(
    const float* __restrict__ in, __nv_bfloat16* __restrict__ oh,
    __nv_bfloat16* __restrict__ ol, int R, int C)
{
    __shared__ float sm[32][33];
    int c0 = blockIdx.x * 32, r0 = blockIdx.y * 32;
    sm[threadIdx.y][threadIdx.x] = in[(size_t)(r0 + threadIdx.y) * C + c0 + threadIdx.x];
    __syncthreads();
    float v = sm[threadIdx.x][threadIdx.y];
    float h = __bfloat162float(__float2bfloat16(v));
    size_t o = (size_t)(c0 + threadIdx.y) * R + r0 + threadIdx.x;
    oh[o] = __float2bfloat16(v);
    ol[o] = __float2bfloat16(v - h);
}

// ---------------- bf16x3 emulated-fp32 GEMM via mma.sync + ldmatrix ----------
// C[M,N] = alpha * A[M,Kt] @ B[N,Kt]^T.  mode 0: fp32 out. mode 1: bf16 hi/lo out.
// Block 128x128, BK=32, 4 warps / 128 threads (warp tile 64x64 — 0.167
// ldsm/HMMA), 3-stage cp.async pipeline, XOR-swizzled dense smem: 96 KB ->
// 2 CTAs/SM (reg ceiling 250/thread at 256 threads/SM), ONE barrier per chunk.
// dual: grid.x doubled; upper half uses Bh2/Bl2 -> Ch2/Cl2 (merged projections).
#define STG  (128 * 32)                       // elements per stage per matrix
#define NSTAGE 3
#define GEMM_SMEM (4 * NSTAGE * STG * 2)      // 96 KB

__global__ __launch_bounds__(128, 2)
void gemm_mma_k(const __nv_bfloat16* __restrict__ Ah, const __nv_bfloat16* __restrict__ Al,
                const __nv_bfloat16* __restrict__ Bh, const __nv_bfloat16* __restrict__ Bl,
                const __nv_bfloat16* __restrict__ Bh2, const __nv_bfloat16* __restrict__ Bl2,
                int Kt, int Nt, int mode, int dual, float alpha,
                float* __restrict__ Cf, __nv_bfloat16* __restrict__ Ch,
                __nv_bfloat16* __restrict__ Cl,
                __nv_bfloat16* __restrict__ Ch2, __nv_bfloat16* __restrict__ Cl2)
{
    extern __shared__ __nv_bfloat16 smem[];
    __nv_bfloat16* sAh = smem;
    __nv_bfloat16* sAl = smem + NSTAGE * STG;
    __nv_bfloat16* sBh = smem + 2 * NSTAGE * STG;
    __nv_bfloat16* sBl = smem + 3 * NSTAGE * STG;
    const uint32_t uAh = smem_to_u32(sAh), uAl = smem_to_u32(sAl);
    const uint32_t uBh = smem_to_u32(sBh), uBl = smem_to_u32(sBl);

    const int tid = threadIdx.x;
    const int wid = tid >> 5, lid = tid & 31;
    const int wm = wid >> 1, wn = wid & 1;        // 2x2 warp grid, warp tile 64x64
    const int g = lid >> 2, t = lid & 3;

    // dual-projection block remap
    int bx = blockIdx.x;
    const __nv_bfloat16* pBh = Bh;
    const __nv_bfloat16* pBl = Bl;
    __nv_bfloat16* pCh = Ch;
    __nv_bfloat16* pCl = Cl;
    const int nblk = Nt >> 7;
    if (dual && bx >= nblk) {
        bx -= nblk;
        pBh = Bh2; pBl = Bl2; pCh = Ch2; pCl = Cl2;
    }
    const int m0 = blockIdx.y * 128, n0 = bx * 128;

    const int crow = tid >> 2, cseg = tid & 3;    // 32 rows per copy pass

    // ldmatrix lane address components
    const int a_row = lid & 15;
    const int a_c   = (lid >> 4) & 1;
    const int b_n   = ((lid >> 4) & 1) * 8 + (lid & 7);
    const int b_c   = (lid >> 3) & 1;

    float acc[4][8][4] = {};                      // 128 regs
    const int nk = Kt >> 5;

    auto load_chunk = [&](int st, int kb) {
        uint32_t so = (uint32_t)(st * STG) * 2;
#pragma unroll
        for (int h = 0; h < 4; h++) {
            int row = crow + h * 32;
            uint32_t sb = so + swz(row, cseg) * 2;
            size_t gA = (size_t)(m0 + row) * Kt + kb + cseg * 8;
            size_t gB = (size_t)(n0 + row) * Kt + kb + cseg * 8;
            cp16(uAh + sb, Ah + gA);
            cp16(uAl + sb, Al + gA);
            cp16(uBh + sb, pBh + gB);
            cp16(uBl + sb, pBl + gB);
        }
    };

    load_chunk(0, 0);
    CP_COMMIT();
    load_chunk(1, 32);
    CP_COMMIT();

    for (int kc = 0; kc < nk; kc++) {
        if (kc + 1 < nk) { CP_WAIT1(); } else { CP_WAIT0(); }
        __syncthreads();                        // single barrier per chunk

        const uint32_t st2 = (uint32_t)((kc % NSTAGE) * STG) * 2;

        // ---- ks = 0 (k chunks 0,1) ----
        uint32_t aH[4][4], aL[4][4], bH[4][4], bL[4][4];
#pragma unroll
        for (int mt = 0; mt < 4; mt++) {
            uint32_t off = st2 + swz(wm * 64 + mt * 16 + a_row, a_c) * 2;
            ldsm4(aH[mt], uAh + off);
            ldsm4(aL[mt], uAl + off);
        }
#pragma unroll
        for (int np = 0; np < 4; np++) {
            uint32_t off = st2 + swz(wn * 64 + np * 16 + b_n, b_c) * 2;
            ldsm4(bH[np], uBh + off);
            ldsm4(bL[np], uBl + off);
        }

        if (kc + 2 < nk) {
            load_chunk((kc + 2) % NSTAGE, (kc + 2) << 5);
            CP_COMMIT();
        }

#pragma unroll
        for (int mt = 0; mt < 4; mt++)
#pragma unroll
            for (int np = 0; np < 4; np++) {
                mma16816(acc[mt][2 * np],     aH[mt], &bH[np][0]);
                mma16816(acc[mt][2 * np],     aH[mt], &bL[np][0]);
                mma16816(acc[mt][2 * np],     aL[mt], &bH[np][0]);
                mma16816(acc[mt][2 * np + 1], aH[mt], &bH[np][2]);
                mma16816(acc[mt][2 * np + 1], aH[mt], &bL[np][2]);
                mma16816(acc[mt][2 * np + 1], aL[mt], &bH[np][2]);
            }

        // ---- ks = 1 (k chunks 2,3) ----
#pragma unroll
        for (int mt = 0; mt < 4; mt++) {
            uint32_t off = st2 + swz(wm * 64 + mt * 16 + a_row, 2 + a_c) * 2;
            ldsm4(aH[mt], uAh + off);
            ldsm4(aL[mt], uAl + off);
        }
#pragma unroll
        for (int np = 0; np < 4; np++) {
            uint32_t off = st2 + swz(wn * 64 + np * 16 + b_n, 2 + b_c) * 2;
            ldsm4(bH[np], uBh + off);
            ldsm4(bL[np], uBl + off);
        }
#pragma unroll
        for (int mt = 0; mt < 4; mt++)
#pragma unroll
            for (int np = 0; np < 4; np++) {
                mma16816(acc[mt][2 * np],     aH[mt], &bH[np][0]);
                mma16816(acc[mt][2 * np],     aH[mt], &bL[np][0]);
                mma16816(acc[mt][2 * np],     aL[mt], &bH[np][0]);
                mma16816(acc[mt][2 * np + 1], aH[mt], &bH[np][2]);
                mma16816(acc[mt][2 * np + 1], aH[mt], &bL[np][2]);
                mma16816(acc[mt][2 * np + 1], aL[mt], &bH[np][2]);
            }
    }

    // ---- epilogue: direct stores ----
#pragma unroll
    for (int mt = 0; mt < 4; mt++) {
#pragma unroll
        for (int nt = 0; nt < 8; nt++) {
            int r = m0 + wm * 64 + mt * 16 + g;
            int c = n0 + wn * 64 + nt * 8 + t * 2;
            float d0 = alpha * acc[mt][nt][0], d1 = alpha * acc[mt][nt][1];
            float d2 = alpha * acc[mt][nt][2], d3 = alpha * acc[mt][nt][3];
            if (mode == 0) {
                float2 v0 = { d0, d1 }, v1 = { d2, d3 };
                *(float2*)(Cf + (size_t)r * Nt + c) = v0;
                *(float2*)(Cf + (size_t)(r + 8) * Nt + c) = v1;
            } else {
                float h0 = __bfloat162float(__float2bfloat16(d0));
                float h1 = __bfloat162float(__float2bfloat16(d1));
                float h2 = __bfloat162float(__float2bfloat16(d2));
                float h3 = __bfloat162float(__float2bfloat16(d3));
                *(uint32_t*)(pCh + (size_t)r * Nt + c)       = pack2bf(d0, d1);
                *(uint32_t*)(pCh + (size_t)(r + 8) * Nt + c) = pack2bf(d2, d3);
                *(uint32_t*)(pCl + (size_t)r * Nt + c)       = pack2bf(d0 - h0, d1 - h1);
                *(uint32_t*)(pCl + (size_t)(r + 8) * Nt + c) = pack2bf(d2 - h2, d3 - h3);
            }
        }
    }
}

// --------------- softmax: fp32 in, bf16 hi/lo split out ----------------------
__global__ __launch_bounds__(256) void softmax_row_k(
    const float* __restrict__ S, __nv_bfloat16* __restrict__ Ph,
    __nv_bfloat16* __restrict__ Pl, int N)
{
    __shared__ float buf[NT];
    __shared__ float red[8];
    const int tid = threadIdx.x;
    const float* row = S + (size_t)blockIdx.x * N;
    __nv_bfloat16* ph = Ph + (size_t)blockIdx.x * N;
    __nv_bfloat16* pl = Pl + (size_t)blockIdx.x * N;

    float m = -1e30f;
    for (int i = tid * 4; i < N; i += 1024) {
        float4 v = *(const float4*)(row + i);
        *(float4*)&buf[i] = v;
        m = fmaxf(m, fmaxf(fmaxf(v.x, v.y), fmaxf(v.z, v.w)));
    }
#pragma unroll
    for (int o = 16; o > 0; o >>= 1) m = fmaxf(m, __shfl_xor_sync(0xffffffffu, m, o));
    if ((tid & 31) == 0) red[tid >> 5] = m;
    __syncthreads();
    if (tid < 32) {
        float v = (tid < 8) ? red[tid] : -1e30f;
#pragma unroll
        for (int o = 4; o > 0; o >>= 1) v = fmaxf(v, __shfl_xor_sync(0xffffffffu, v, o));
        if (tid == 0) red[0] = v;
    }
    __syncthreads();
    const float gm = red[0];
    __syncthreads();

    float s = 0.0f;
    for (int i = tid * 4; i < N; i += 1024) {
        float4 v = *(float4*)&buf[i];
        v.x = expf(v.x - gm); v.y = expf(v.y - gm);
        v.z = expf(v.z - gm); v.w = expf(v.w - gm);
        *(float4*)&buf[i] = v;
        s += (v.x + v.y) + (v.z + v.w);
    }
#pragma unroll
    for (int o = 16; o > 0; o >>= 1) s += __shfl_xor_sync(0xffffffffu, s, o);
    if ((tid & 31) == 0) red[tid >> 5] = s;
    __syncthreads();
    if (tid < 32) {
        float v = (tid < 8) ? red[tid] : 0.0f;
#pragma unroll
        for (int o = 4; o > 0; o >>= 1) v += __shfl_xor_sync(0xffffffffu, v, o);
        if (tid == 0) red[0] = v;
    }
    __syncthreads();
    const float inv = 1.0f / red[0];

    for (int i = tid * 4; i < N; i += 1024) {
        float4 v = *(float4*)&buf[i];
        v.x *= inv; v.y *= inv; v.z *= inv; v.w *= inv;
        float hx = __bfloat162float(__float2bfloat16(v.x));
        float hy = __bfloat162float(__float2bfloat16(v.y));
        float hz = __bfloat162float(__float2bfloat16(v.z));
        float hw = __bfloat162float(__float2bfloat16(v.w));
        uint2 H, L;
        H.x = pack2bf(v.x, v.y);            H.y = pack2bf(v.z, v.w);
        L.x = pack2bf(v.x - hx, v.y - hy);  L.y = pack2bf(v.z - hz, v.w - hw);
        *(uint2*)(ph + i) = H;
        *(uint2*)(pl + i) = L;
    }
}

// -----------------------------------------------------------------------------
extern "C" void kernel_launch(void* const* d_in, const int* in_sizes, int n_in,
                              void* d_out, int out_size)
{
    const float* Wq = (const float*)d_in[0];
    const float* Wk = (const float*)d_in[1];
    const float* X  = (const float*)d_in[2];
    float* O = (float*)d_out;

    float* S;
    __nv_bfloat16 *Xh, *Xl, *XTh, *XTl, *Wqth, *Wqtl, *Wkth, *Wktl;
    __nv_bfloat16 *Qh, *Ql, *Kh, *Kl, *Ph, *Pl;
    cudaGetSymbolAddress((void**)&S, g_S);
    cudaGetSymbolAddress((void**)&Xh, g_Xh);     cudaGetSymbolAddress((void**)&Xl, g_Xl);
    cudaGetSymbolAddress((void**)&XTh, g_XTh);   cudaGetSymbolAddress((void**)&XTl, g_XTl);
    cudaGetSymbolAddress((void**)&Wqth, g_Wqth); cudaGetSymbolAddress((void**)&Wqtl, g_Wqtl);
    cudaGetSymbolAddress((void**)&Wkth, g_Wkth); cudaGetSymbolAddress((void**)&Wktl, g_Wktl);
    cudaGetSymbolAddress((void**)&Qh, g_Qh);     cudaGetSymbolAddress((void**)&Ql, g_Ql);
    cudaGetSymbolAddress((void**)&Kh, g_Kh);     cudaGetSymbolAddress((void**)&Kl, g_Kl);
    cudaGetSymbolAddress((void**)&Ph, g_Ph);     cudaGetSymbolAddress((void**)&Pl, g_Pl);

    cudaFuncSetAttribute(gemm_mma_k, cudaFuncAttributeMaxDynamicSharedMemorySize, GEMM_SMEM);

    // operand prep
    split_k<<<(NT * ED / 4 + 255) / 256, 256>>>(X, Xh, Xl, NT * ED / 4);
    tsplit_k<<<dim3(ED / 32, ED / 32), dim3(32, 32)>>>(Wq, Wqth, Wqtl, ED, ED);
    tsplit_k<<<dim3(ED / 32, ED / 32), dim3(32, 32)>>>(Wk, Wkth, Wktl, ED, ED);
    tsplit_k<<<dim3(ED / 32, NT / 32), dim3(32, 32)>>>(X, XTh, XTl, NT, ED);

    // Q = X @ Wq AND K = X @ Wk in one merged launch (dual=1, grid.x doubled)
    gemm_mma_k<<<dim3(2 * ED / 128, NT / 128), 128, GEMM_SMEM>>>(
        Xh, Xl, Wqth, Wqtl, Wkth, Wktl, ED, ED, 1, 1, 1.0f,
        nullptr, Qh, Ql, Kh, Kl);

    // S = (Q @ K^T) / 32
    gemm_mma_k<<<dim3(NT / 128, NT / 128), 128, GEMM_SMEM>>>(
        Qh, Ql, Kh, Kl, nullptr, nullptr, ED, NT, 0, 0, 0.03125f,
        S, nullptr, nullptr, nullptr, nullptr);

    // P = softmax(S), split to bf16 hi/lo
    softmax_row_k<<<NT, 256>>>(S, Ph, Pl, NT);

    // O = P @ X
    gemm_mma_k<<<dim3(ED / 128, NT / 128), 128, GEMM_SMEM>>>(
        Ph, Pl, XTh, XTl, nullptr, nullptr, NT, ED, 0, 0, 1.0f,
        O, nullptr, nullptr, nullptr, nullptr);
}